// round 1
// baseline (speedup 1.0000x reference)
#include <cuda_runtime.h>

// LocalWindowAttention3D fused kernel.
// One CTA per (batch, window). 256 threads, ~194KB dynamic smem, 1 CTA/SM.
//
// Phases:
//   A: gather x window (128 ch x 64 tokens) into smem (float4 over w-runs)
//   B: qkv = Wqkv @ x_tile, 3 passes of 128 rows; Wqkv chunk staged transposed
//      in smem (pitch 132 -> conflict-free STS.128/LDS.128)
//   C: per-head 64x64 scores -> softmax (no max-sub needed: |logit| <~ 25)
//   D: P @ V into attention-out tile (c-major in smem)
//   E: out = Wout @ ao + bout, written contiguously at out[b, c, n*64 + t]
//      (the reference's window-order reinterpretation makes writes contiguous)

namespace {
constexpr int CDIM = 128;
constexpr int SDIM = 48 * 48 * 48;      // 110592
constexpr int NWIN = 12 * 12 * 12;      // 1728 windows per batch
// smem layout (floats):
//   qkv : 384*64            = 24576
//   ws  : 128*132           = 16896   (weight chunk; aliased by sc/psum/pT)
//   xs  : 128*64            =  8192   (aliased by ao)
constexpr int OFF_QKV = 0;
constexpr int OFF_WS  = 24576;
constexpr int OFF_XS  = 24576 + 16896;
constexpr int SMEM_FLOATS = 24576 + 16896 + 8192;   // 49664
constexpr int SMEM_BYTES  = SMEM_FLOATS * 4;        // 198656
}

__global__ __launch_bounds__(256, 1)
void lwa3d_fused(const float* __restrict__ x, const float* __restrict__ Wqkv,
                 const float* __restrict__ Wout, const float* __restrict__ bout,
                 float* __restrict__ out)
{
    extern __shared__ float sm[];
    float* qkv  = sm + OFF_QKV;          // [384][64]
    float* ws   = sm + OFF_WS;           // [128][132] weight chunk (transposed)
    float* xs   = sm + OFF_XS;           // [128][64]
    float* sc   = ws;                    // [64][65] raw scores
    float* psum = ws + 64 * 65;          // [4][64] partial softmax sums
    float* pT   = ws + 64 * 65 + 256;    // [64][64] normalized probs, k-major
    float* ao   = xs;                    // [128][64] attention out (c-major)

    const int tid = threadIdx.x;
    const int n   = blockIdx.x;          // window index
    const int b   = blockIdx.y;
    const int ndi = n / 144;
    const int nhi = (n / 12) % 12;
    const int nwi = n % 12;

    const float* xb = x + (size_t)b * CDIM * SDIM;

    // ---------------- Phase A: gather x window ----------------
    {
        const int sbase = ((ndi * 4) * 48 + nhi * 4) * 48 + nwi * 4;
        for (int i = tid; i < CDIM * 16; i += 256) {
            const int c = i >> 4;
            const int g = i & 15;               // token group: t = g*4 + ww
            const int wdi = g >> 2, whi = g & 3;
            const int s0 = sbase + (wdi * 48 + whi) * 48;
            const float4 v = *reinterpret_cast<const float4*>(xb + (size_t)c * SDIM + s0);
            *reinterpret_cast<float4*>(xs + c * 64 + g * 4) = v;
        }
    }
    __syncthreads();

    const int tt = tid & 15;   // token group (4 tokens)
    const int te = tid >> 4;   // output-row group (8 rows)

    // ---------------- Phase B: qkv = Wqkv @ x ----------------
    for (int pass = 0; pass < 3; ++pass) {
        const float* Wp = Wqkv + (size_t)pass * 128 * CDIM;
        // stage 128x128 chunk transposed: ws[c*132 + e]
        for (int i = tid; i < 32 * CDIM; i += 256) {
            const int c  = i & 127;
            const int e4 = i >> 7;
            const float a0 = __ldg(Wp + (e4 * 4 + 0) * CDIM + c);
            const float a1 = __ldg(Wp + (e4 * 4 + 1) * CDIM + c);
            const float a2 = __ldg(Wp + (e4 * 4 + 2) * CDIM + c);
            const float a3 = __ldg(Wp + (e4 * 4 + 3) * CDIM + c);
            *reinterpret_cast<float4*>(ws + c * 132 + e4 * 4) = make_float4(a0, a1, a2, a3);
        }
        __syncthreads();

        float acc[8][4];
        #pragma unroll
        for (int r = 0; r < 8; ++r)
            #pragma unroll
            for (int j = 0; j < 4; ++j) acc[r][j] = 0.f;

        #pragma unroll 4
        for (int c = 0; c < CDIM; ++c) {
            const float4 xv = *reinterpret_cast<const float4*>(xs + c * 64 + tt * 4);
            const float4 wa = *reinterpret_cast<const float4*>(ws + c * 132 + te * 8);
            const float4 wb = *reinterpret_cast<const float4*>(ws + c * 132 + te * 8 + 4);
            const float w[8]  = {wa.x, wa.y, wa.z, wa.w, wb.x, wb.y, wb.z, wb.w};
            const float xx[4] = {xv.x, xv.y, xv.z, xv.w};
            #pragma unroll
            for (int r = 0; r < 8; ++r)
                #pragma unroll
                for (int j = 0; j < 4; ++j)
                    acc[r][j] = fmaf(w[r], xx[j], acc[r][j]);
        }
        #pragma unroll
        for (int r = 0; r < 8; ++r)
            *reinterpret_cast<float4*>(qkv + (pass * 128 + te * 8 + r) * 64 + tt * 4) =
                make_float4(acc[r][0], acc[r][1], acc[r][2], acc[r][3]);
        __syncthreads();
    }

    // ---------------- Phase C/D: windowed attention ----------------
    const float scale = 0.08838834764831845f;   // 128^-0.5
    const int q_   = tid & 63;
    const int part = tid >> 6;                  // 0..3
    const int qg   = tid & 15;
    const int kg   = tid >> 4;

    for (int h = 0; h < 8; ++h) {
        const float* qh = qkv + (h * 16) * 64;
        const float* kh = qkv + (128 + h * 16) * 64;
        const float* vh = qkv + (256 + h * 16) * 64;

        // scores: thread computes 4q x 4k tile
        float s4[4][4];
        #pragma unroll
        for (int a2 = 0; a2 < 4; ++a2)
            #pragma unroll
            for (int b2 = 0; b2 < 4; ++b2) s4[a2][b2] = 0.f;

        #pragma unroll
        for (int e = 0; e < 16; ++e) {
            const float4 qv = *reinterpret_cast<const float4*>(qh + e * 64 + qg * 4);
            const float4 kv = *reinterpret_cast<const float4*>(kh + e * 64 + kg * 4);
            const float qa[4] = {qv.x, qv.y, qv.z, qv.w};
            const float ka[4] = {kv.x, kv.y, kv.z, kv.w};
            #pragma unroll
            for (int a2 = 0; a2 < 4; ++a2)
                #pragma unroll
                for (int b2 = 0; b2 < 4; ++b2)
                    s4[a2][b2] = fmaf(qa[a2], ka[b2], s4[a2][b2]);
        }
        #pragma unroll
        for (int a2 = 0; a2 < 4; ++a2)
            #pragma unroll
            for (int b2 = 0; b2 < 4; ++b2)
                sc[(qg * 4 + a2) * 65 + kg * 4 + b2] = s4[a2][b2];
        __syncthreads();

        // softmax: partial exp-sums (logits bounded ~ +-25, no max-sub needed)
        float lsum = 0.f;
        #pragma unroll
        for (int k = 0; k < 16; ++k)
            lsum += __expf(sc[q_ * 65 + part * 16 + k] * scale);
        psum[part * 64 + q_] = lsum;
        __syncthreads();
        const float tot  = psum[q_] + psum[64 + q_] + psum[128 + q_] + psum[192 + q_];
        const float rinv = 1.f / tot;
        #pragma unroll
        for (int k = 0; k < 16; ++k) {
            const int kk = part * 16 + k;
            pT[kk * 64 + q_] = __expf(sc[q_ * 65 + kk] * scale) * rinv;
        }
        __syncthreads();

        // P @ V: thread owns (query q_, 4 head-dims part*4..part*4+3)
        float oacc[4] = {0.f, 0.f, 0.f, 0.f};
        #pragma unroll 4
        for (int k4 = 0; k4 < 16; ++k4) {
            const float p0 = pT[(k4 * 4 + 0) * 64 + q_];
            const float p1 = pT[(k4 * 4 + 1) * 64 + q_];
            const float p2 = pT[(k4 * 4 + 2) * 64 + q_];
            const float p3 = pT[(k4 * 4 + 3) * 64 + q_];
            #pragma unroll
            for (int j = 0; j < 4; ++j) {
                const float4 vv = *reinterpret_cast<const float4*>(vh + (part * 4 + j) * 64 + k4 * 4);
                oacc[j] = fmaf(p0, vv.x, oacc[j]);
                oacc[j] = fmaf(p1, vv.y, oacc[j]);
                oacc[j] = fmaf(p2, vv.z, oacc[j]);
                oacc[j] = fmaf(p3, vv.w, oacc[j]);
            }
        }
        __syncthreads();   // everyone done reading sc/pT before next head rewrites them
        #pragma unroll
        for (int j = 0; j < 4; ++j)
            ao[(h * 16 + part * 4 + j) * 64 + q_] = oacc[j];
    }

    // ---------------- Phase E: out = Wout @ ao + bout ----------------
    for (int i = tid; i < 32 * CDIM; i += 256) {
        const int c  = i & 127;
        const int e4 = i >> 7;
        const float a0 = __ldg(Wout + (e4 * 4 + 0) * CDIM + c);
        const float a1 = __ldg(Wout + (e4 * 4 + 1) * CDIM + c);
        const float a2 = __ldg(Wout + (e4 * 4 + 2) * CDIM + c);
        const float a3 = __ldg(Wout + (e4 * 4 + 3) * CDIM + c);
        *reinterpret_cast<float4*>(ws + c * 132 + e4 * 4) = make_float4(a0, a1, a2, a3);
    }
    __syncthreads();

    float acc[8][4];
    #pragma unroll
    for (int r = 0; r < 8; ++r)
        #pragma unroll
        for (int j = 0; j < 4; ++j) acc[r][j] = 0.f;

    #pragma unroll 4
    for (int c = 0; c < CDIM; ++c) {
        const float4 av = *reinterpret_cast<const float4*>(ao + c * 64 + tt * 4);
        const float4 wa = *reinterpret_cast<const float4*>(ws + c * 132 + te * 8);
        const float4 wb = *reinterpret_cast<const float4*>(ws + c * 132 + te * 8 + 4);
        const float w[8]  = {wa.x, wa.y, wa.z, wa.w, wb.x, wb.y, wb.z, wb.w};
        const float aa[4] = {av.x, av.y, av.z, av.w};
        #pragma unroll
        for (int r = 0; r < 8; ++r)
            #pragma unroll
            for (int j = 0; j < 4; ++j)
                acc[r][j] = fmaf(w[r], aa[j], acc[r][j]);
    }

    float* ob = out + (size_t)b * CDIM * SDIM + n * 64;
    #pragma unroll
    for (int r = 0; r < 8; ++r) {
        const int e = te * 8 + r;
        const float bb = __ldg(bout + e);
        *reinterpret_cast<float4*>(ob + (size_t)e * SDIM + tt * 4) =
            make_float4(acc[r][0] + bb, acc[r][1] + bb, acc[r][2] + bb, acc[r][3] + bb);
    }
}

extern "C" void kernel_launch(void* const* d_in, const int* in_sizes, int n_in,
                              void* d_out, int out_size)
{
    const float* x    = (const float*)d_in[0];
    const float* Wqkv = (const float*)d_in[1];
    const float* Wout = (const float*)d_in[2];
    const float* bout = (const float*)d_in[3];
    float* out = (float*)d_out;

    cudaFuncSetAttribute(lwa3d_fused, cudaFuncAttributeMaxDynamicSharedMemorySize, SMEM_BYTES);

    dim3 grid(NWIN, 2);
    dim3 block(256);
    lwa3d_fused<<<grid, block, SMEM_BYTES>>>(x, Wqkv, Wout, bout, out);
}